// round 3
// baseline (speedup 1.0000x reference)
#include <cuda_runtime.h>
#include <cuda_bf16.h>
#include <cstdint>

// ---------------- problem constants ----------------
#define BATCH    64
#define INCH     8192
#define OUTCH    8192
#define NT       64             // out-channel tile per CTA
#define KT       64             // K tile (64 bf16 = 128B row)
#define NITER    (INCH / KT)    // 128
#define NTHREADS 256
#define NCTAS    (OUTCH / NT)   // 128

// smem: A stages 128x128B = 16KB each, B stages 64x128B = 8KB each
#define SMEM_BYTES 49152

__device__ __nv_bfloat16 g_xsplit[(size_t)2 * BATCH * INCH]; // rows 0..63 hi, 64..127 lo
__device__ float g_abssum;

// ---------------- helpers ----------------
__device__ __forceinline__ uint32_t smem_u32(const void* p) {
    uint32_t a;
    asm("{ .reg .u64 t; cvta.to.shared.u64 t, %1; cvt.u32.u64 %0, t; }" : "=r"(a) : "l"(p));
    return a;
}

#define SW128(off) ((off) ^ (((off) >> 3) & 0x70))

__device__ __forceinline__ uint32_t sgn_bf16(float w) {
    uint32_t u = __float_as_uint(w);
    return (w == 0.0f) ? 0u : (0x3F80u | ((u >> 16) & 0x8000u));
}

__device__ __forceinline__ void ldsm_x4(uint32_t* r, uint32_t addr) {
    asm volatile("ldmatrix.sync.aligned.m8n8.x4.shared.b16 {%0,%1,%2,%3}, [%4];"
                 : "=r"(r[0]), "=r"(r[1]), "=r"(r[2]), "=r"(r[3]) : "r"(addr));
}

__device__ __forceinline__ void mma_bf16(float* c, const uint32_t* a, const uint32_t* b) {
    asm volatile(
        "mma.sync.aligned.m16n8k16.row.col.f32.bf16.bf16.f32 "
        "{%0,%1,%2,%3}, {%4,%5,%6,%7}, {%8,%9}, {%0,%1,%2,%3};"
        : "+f"(c[0]), "+f"(c[1]), "+f"(c[2]), "+f"(c[3])
        : "r"(a[0]), "r"(a[1]), "r"(a[2]), "r"(a[3]), "r"(b[0]), "r"(b[1]));
}

__device__ __forceinline__ void cp_async16(uint32_t dst, const void* src) {
    asm volatile("cp.async.cg.shared.global [%0], [%1], 16;"
                 :: "r"(dst), "l"(__cvta_generic_to_global(src)) : "memory");
}
#define CP_COMMIT() asm volatile("cp.async.commit_group;" ::: "memory")
#define CP_WAIT0()  asm volatile("cp.async.wait_group 0;" ::: "memory")

// ---------------- kernel 0: split x into bf16 hi/lo planes ----------------
__global__ void hb_split_kernel(const float* __restrict__ x) {
    int i = blockIdx.x * blockDim.x + threadIdx.x;
    if (i == 0) g_abssum = 0.0f;
    if (i < BATCH * INCH) {
        float v = x[i];
        __nv_bfloat16 h = __float2bfloat16(v);
        float r = v - __bfloat162float(h);
        g_xsplit[i] = h;
        g_xsplit[i + (size_t)BATCH * INCH] = __float2bfloat16(r);
    }
}

// ---------------- kernel 1: fused sign + mma.sync GEMM + |W| reduce ----------------
__global__ void __launch_bounds__(NTHREADS, 1)
hb_gemm_kernel(const float* __restrict__ W, float* __restrict__ out) {
    __shared__ __align__(1024) char smem[SMEM_BYTES];
    const uint32_t sb = smem_u32(smem);

    const int tid  = threadIdx.x;
    const int lane = tid & 31;
    const int wid  = tid >> 5;
    const int wm   = wid & 1;          // 2 warps along M
    const int wn   = wid >> 1;         // 4 warps along N
    const int n0   = blockIdx.x * NT;
    const int m0   = wm * 32;          // batch rows (hi plane); lo plane at +64
    const int nw   = wn * 16;          // warp's n offset within CTA tile

    const uint32_t A_st[2] = { sb,          sb + 16384 };
    const uint32_t B_st[2] = { sb + 32768,  sb + 40960 };

    float c[2][2][4];
#pragma unroll
    for (int mt = 0; mt < 2; mt++)
#pragma unroll
        for (int nt = 0; nt < 2; nt++)
#pragma unroll
            for (int r = 0; r < 4; r++) c[mt][nt][r] = 0.0f;

    float absacc = 0.0f;
    float4 wv[4];   // 16 staged W floats

    // ldmatrix per-lane coordinates
    const int arow = lane & 15;                       // A: row within m16 tile
    const int ac8  = lane >> 4;                       // A: k chunk (0/1)
    const int brow = nw + (lane & 7) + ((lane >> 4) << 3); // B: n row
    const int bc8  = (lane >> 3) & 1;                 // B: k chunk (0/1)

    // W load/store coords: 2 groups of 8 contiguous floats
    int wrow[2], wkc[2];
#pragma unroll
    for (int g = 0; g < 2; g++) { int cid = tid + g * NTHREADS; wrow[g] = cid >> 3; wkc[g] = cid & 7; }
    // A cp.async coords: 4 groups of 16B
    int xrow[4], xc8[4];
#pragma unroll
    for (int g = 0; g < 4; g++) { int cid = tid + g * NTHREADS; xrow[g] = cid >> 3; xc8[g] = cid & 7; }

#define LOADW(it) do { \
    int _k0 = (it) * KT; \
    _Pragma("unroll") \
    for (int g = 0; g < 2; g++) { \
        const float4* p = reinterpret_cast<const float4*>( \
            W + (size_t)(n0 + wrow[g]) * INCH + _k0 + wkc[g] * 8); \
        wv[2*g]   = p[0]; \
        wv[2*g+1] = p[1]; \
    } \
} while (0)

#define CPA(it, st) do { \
    int _k0 = (it) * KT; \
    _Pragma("unroll") \
    for (int g = 0; g < 4; g++) { \
        const __nv_bfloat16* src = g_xsplit + (size_t)xrow[g] * INCH + _k0 + xc8[g] * 8; \
        cp_async16(A_st[st] + SW128((uint32_t)(xrow[g] * 128 + xc8[g] * 16)), src); \
    } \
    CP_COMMIT(); \
} while (0)

#define STSW(st) do { \
    _Pragma("unroll") \
    for (int g = 0; g < 2; g++) { \
        float f0 = wv[2*g].x, f1 = wv[2*g].y, f2 = wv[2*g].z, f3 = wv[2*g].w; \
        float f4 = wv[2*g+1].x, f5 = wv[2*g+1].y, f6 = wv[2*g+1].z, f7 = wv[2*g+1].w; \
        absacc += fabsf(f0)+fabsf(f1)+fabsf(f2)+fabsf(f3)+fabsf(f4)+fabsf(f5)+fabsf(f6)+fabsf(f7); \
        uint32_t p0 = sgn_bf16(f0) | (sgn_bf16(f1) << 16); \
        uint32_t p1 = sgn_bf16(f2) | (sgn_bf16(f3) << 16); \
        uint32_t p2 = sgn_bf16(f4) | (sgn_bf16(f5) << 16); \
        uint32_t p3 = sgn_bf16(f6) | (sgn_bf16(f7) << 16); \
        asm volatile("st.shared.v4.b32 [%0], {%1,%2,%3,%4};" \
                     :: "r"(B_st[st] + SW128((uint32_t)(wrow[g] * 128 + wkc[g] * 16))), \
                        "r"(p0), "r"(p1), "r"(p2), "r"(p3) : "memory"); \
    } \
} while (0)

#define COMPUTE(st) do { \
    _Pragma("unroll") \
    for (int ks = 0; ks < 4; ks++) { \
        uint32_t bf[4]; \
        ldsm_x4(bf, B_st[st] + SW128((uint32_t)(brow * 128 + ks * 32 + bc8 * 16))); \
        _Pragma("unroll") \
        for (int pl = 0; pl < 2; pl++) { \
            _Pragma("unroll") \
            for (int mt = 0; mt < 2; mt++) { \
                uint32_t af[4]; \
                int row = pl * 64 + m0 + mt * 16 + arow; \
                ldsm_x4(af, A_st[st] + SW128((uint32_t)(row * 128 + ks * 32 + ac8 * 16))); \
                mma_bf16(c[mt][0], af, bf); \
                mma_bf16(c[mt][1], af, bf + 2); \
            } \
        } \
    } \
} while (0)

    // prologue: stage 0
    LOADW(0);
    CPA(0, 0);
    STSW(0);
    CP_WAIT0();
    __syncthreads();

    for (int it = 0; it < NITER; ++it) {
        const int cur = it & 1, nxt = cur ^ 1;
        if (it + 1 < NITER) {
            LOADW(it + 1);
            CPA(it + 1, nxt);
        }
        COMPUTE(cur);
        if (it + 1 < NITER) {
            STSW(nxt);
            CP_WAIT0();
            __syncthreads();
        }
    }

    // |W| warp reduce + one atomic per warp
#pragma unroll
    for (int o = 16; o > 0; o >>= 1) absacc += __shfl_xor_sync(0xFFFFFFFFu, absacc, o);
    if (lane == 0) atomicAdd(&g_abssum, absacc);

    // epilogue: registers -> global (unscaled; kernel 2 applies mean|W|)
#pragma unroll
    for (int mt = 0; mt < 2; mt++) {
#pragma unroll
        for (int nt = 0; nt < 2; nt++) {
            int col = n0 + nw + nt * 8 + (lane & 3) * 2;
            int r0  = m0 + mt * 16 + (lane >> 2);
            float2* o0 = reinterpret_cast<float2*>(out + (size_t)r0 * OUTCH + col);
            float2* o1 = reinterpret_cast<float2*>(out + (size_t)(r0 + 8) * OUTCH + col);
            *o0 = make_float2(c[mt][nt][0], c[mt][nt][1]);
            *o1 = make_float2(c[mt][nt][2], c[mt][nt][3]);
        }
    }

#undef LOADW
#undef CPA
#undef STSW
#undef COMPUTE
}

// ---------------- kernel 2: apply scale = mean(|W|) ----------------
__global__ void hb_scale_kernel(float* __restrict__ out) {
    float s = g_abssum * (1.0f / ((float)INCH * (float)OUTCH));
    int i = blockIdx.x * blockDim.x + threadIdx.x;
    float4* o = reinterpret_cast<float4*>(out);
    float4 v = o[i];
    v.x *= s; v.y *= s; v.z *= s; v.w *= s;
    o[i] = v;
}

// ---------------- launch ----------------
extern "C" void kernel_launch(void* const* d_in, const int* in_sizes, int n_in,
                              void* d_out, int out_size) {
    const float* x = (const float*)d_in[0];
    const float* w = (const float*)d_in[1];
    if (n_in >= 2 && in_sizes[0] != BATCH * INCH) { const float* t = x; x = w; w = t; }
    float* out = (float*)d_out;

    hb_split_kernel<<<(BATCH * INCH + 255) / 256, 256>>>(x);
    hb_gemm_kernel<<<NCTAS, NTHREADS>>>(w, out);
    hb_scale_kernel<<<(BATCH * OUTCH / 4) / 256, 256>>>(out);
}